// round 1
// baseline (speedup 1.0000x reference)
#include <cuda_runtime.h>

// Problem constants (fixed by the dataset: B=16, N=8192, C=256, num_points=2048)
#define BB   16
#define NN   8192
#define CC   256
#define MM   2048
#define TT   1024          // threads per FPS block
#define PPT  (NN / TT)     // points per thread = 8

// Scratch: selected indices, written by FPS kernel, read by gather kernel.
__device__ int g_idx[BB * MM];

// Dynamic smem layout: sx[NN], sy[NN], sz[NN], pv[64], pi[64], cent[96]
#define SMEM_BYTES (3 * NN * 4 + 64 * 4 + 64 * 4 + 96 * 4)

__device__ __forceinline__ float warp_sum(float x) {
    #pragma unroll
    for (int o = 16; o > 0; o >>= 1)
        x += __shfl_xor_sync(0xFFFFFFFFu, x, o);
    return x;
}

// Block-wide argmax of (v, i) with first-index tie-break (matches jnp.argmax).
// v must be a non-negative float. One __syncthreads per call; callers must
// strictly alternate `buf` between consecutive calls (double-buffered partials).
__device__ __forceinline__ unsigned block_argmax(float v, unsigned i, int buf,
                                                 unsigned* pv, unsigned* pi,
                                                 int warp, int lane)
{
    unsigned vb = __float_as_uint(v);            // monotone for v >= 0
    unsigned m1 = __reduce_max_sync(0xFFFFFFFFu, vb);
    unsigned c1 = (vb == m1) ? i : 0xFFFFFFFFu;
    unsigned i1 = __reduce_min_sync(0xFFFFFFFFu, c1);
    if (lane == 0) { pv[buf * 32 + warp] = m1; pi[buf * 32 + warp] = i1; }
    __syncthreads();
    unsigned v2 = pv[buf * 32 + lane];
    unsigned i2 = pi[buf * 32 + lane];
    unsigned m2 = __reduce_max_sync(0xFFFFFFFFu, v2);
    unsigned c2 = (v2 == m2) ? i2 : 0xFFFFFFFFu;
    return __reduce_min_sync(0xFFFFFFFFu, c2);
}

extern "C" __global__ void __launch_bounds__(TT, 1)
fps_kernel(const float* __restrict__ pts,   // [B, 3, N]
           float* __restrict__ out_pts)     // [B, M, 3]
{
    extern __shared__ unsigned char smraw[];
    float*    sx   = (float*)smraw;
    float*    sy   = sx + NN;
    float*    sz   = sy + NN;
    unsigned* pv   = (unsigned*)(sz + NN);
    unsigned* pi   = pv + 64;
    float*    cent = (float*)(pi + 64);

    const int b    = blockIdx.x;
    const int tid  = threadIdx.x;
    const int lane = tid & 31;
    const int warp = tid >> 5;

    const float* px = pts + (size_t)b * 3 * NN;
    const float* py = px + NN;
    const float* pz = px + 2 * NN;

    // Load points into registers (and a read-only smem copy for broadcasts).
    float xr[PPT], yr[PPT], zr[PPT], dr[PPT];
    float s1 = 0.f, s2 = 0.f, s3 = 0.f;
    #pragma unroll
    for (int k = 0; k < PPT; k++) {
        int n = tid + k * TT;               // coalesced, ascending per-thread
        float x = px[n], y = py[n], z = pz[n];
        xr[k] = x; yr[k] = y; zr[k] = z;
        sx[n] = x; sy[n] = y; sz[n] = z;
        s1 += x; s2 += y; s3 += z;
        dr[k] = 1e10f;
    }

    // Deterministic centroid: warp tree-sum -> smem partials -> warp tree-sum.
    s1 = warp_sum(s1); s2 = warp_sum(s2); s3 = warp_sum(s3);
    if (lane == 0) { cent[warp] = s1; cent[32 + warp] = s2; cent[64 + warp] = s3; }
    __syncthreads();
    float cx = warp_sum(cent[lane])      * (1.0f / NN);
    float cy = warp_sum(cent[32 + lane]) * (1.0f / NN);
    float cz = warp_sum(cent[64 + lane]) * (1.0f / NN);

    // d0 = ||p - centroid||^2, initial farthest = argmax(d0).
    // No FMA contraction: match plain elementwise fp32 evaluation.
    float best = -1.0f; unsigned bi = 0;
    #pragma unroll
    for (int k = 0; k < PPT; k++) {
        float dx = xr[k] - cx, dy = yr[k] - cy, dz = zr[k] - cz;
        float d = __fadd_rn(__fadd_rn(__fmul_rn(dx, dx), __fmul_rn(dy, dy)),
                            __fmul_rn(dz, dz));
        if (d > best) { best = d; bi = (unsigned)(tid + k * TT); }
    }
    unsigned far = block_argmax(best, bi, 0, pv, pi, warp, lane);

    float* outp = out_pts + (size_t)b * MM * 3;
    int*   idxp = g_idx + b * MM;

    for (int m = 0; m < MM; m++) {
        // Broadcast the selected point's coords from the read-only smem copy.
        float qx = sx[far], qy = sy[far], qz = sz[far];
        if (tid == 0) {
            idxp[m] = (int)far;
            outp[m * 3 + 0] = qx;
            outp[m * 3 + 1] = qy;
            outp[m * 3 + 2] = qz;
        }
        float bst = -1.0f; unsigned bix = 0;
        #pragma unroll
        for (int k = 0; k < PPT; k++) {
            float dx = xr[k] - qx, dy = yr[k] - qy, dz = zr[k] - qz;
            float d = __fadd_rn(__fadd_rn(__fmul_rn(dx, dx), __fmul_rn(dy, dy)),
                                __fmul_rn(dz, dz));
            float nd = fminf(dr[k], d);
            dr[k] = nd;
            if (nd > bst) { bst = nd; bix = (unsigned)(tid + k * TT); }
        }
        far = block_argmax(bst, bix, (m + 1) & 1, pv, pi, warp, lane);
    }
}

extern "C" __global__ void gather_kernel(const float* __restrict__ feats,  // [B, C, N]
                                         float* __restrict__ out_feats)   // [B, M, C]
{
    int bm = blockIdx.x;                 // b * MM + m
    int b  = bm >> 11;                   // MM = 2048
    int n  = g_idx[bm];
    int c  = threadIdx.x;                // 0..CC-1
    out_feats[(size_t)bm * CC + c] = feats[((size_t)b * CC + c) * NN + n];
}

extern "C" void kernel_launch(void* const* d_in, const int* in_sizes, int n_in,
                              void* d_out, int out_size)
{
    const float* pts   = (const float*)d_in[0];  // [B, 3, N]
    const float* feats = (const float*)d_in[1];  // [B, C, N]
    float* out = (float*)d_out;

    // Allow >48KB dynamic smem (immediate host-side attr set; not a stream op,
    // safe under graph capture; idempotent).
    cudaFuncSetAttribute(fps_kernel,
                         cudaFuncAttributeMaxDynamicSharedMemorySize, SMEM_BYTES);

    fps_kernel<<<BB, TT, SMEM_BYTES>>>(pts, out);
    gather_kernel<<<BB * MM, CC>>>(feats, out + (size_t)BB * MM * 3);
}

// round 2
// speedup vs baseline: 1.2924x; 1.2924x over previous
#include <cuda_runtime.h>

// Problem constants (fixed: B=16, N=8192, C=256, num_points=2048)
#define BB   16
#define NN   8192
#define CC   256
#define MM   2048
#define TT   1024          // threads per FPS block
#define PPT  (NN / TT)     // points per thread = 8
#define NPAIR (PPT / 2)    // f32x2 pairs per thread = 4

// Scratch: selected indices, written by FPS kernel, read by gather kernel.
__device__ int g_idx[BB * MM];

// Dynamic smem: sx[NN], sy[NN], sz[NN], pv[64], pi[64], cent[96]
#define SMEM_BYTES (3 * NN * 4 + 64 * 4 + 64 * 4 + 96 * 4)

// ---- packed f32x2 helpers (sm_103a) ---------------------------------------
__device__ __forceinline__ unsigned long long pack2(float lo, float hi) {
    unsigned long long r;
    asm("mov.b64 %0, {%1, %2};" : "=l"(r) : "f"(lo), "f"(hi));
    return r;
}
__device__ __forceinline__ void unpack2(unsigned long long v, float& lo, float& hi) {
    asm("mov.b64 {%0, %1}, %2;" : "=f"(lo), "=f"(hi) : "l"(v));
}
__device__ __forceinline__ unsigned long long add2(unsigned long long a, unsigned long long b) {
    unsigned long long r;
    asm("add.rn.f32x2 %0, %1, %2;" : "=l"(r) : "l"(a), "l"(b));
    return r;
}
__device__ __forceinline__ unsigned long long mul2(unsigned long long a, unsigned long long b) {
    unsigned long long r;
    asm("mul.rn.f32x2 %0, %1, %2;" : "=l"(r) : "l"(a), "l"(b));
    return r;
}
// ---------------------------------------------------------------------------

__device__ __forceinline__ float warp_sum(float x) {
    #pragma unroll
    for (int o = 16; o > 0; o >>= 1)
        x += __shfl_xor_sync(0xFFFFFFFFu, x, o);
    return x;
}

// Block-wide argmax of (v, i), first-index tie-break (matches jnp.argmax).
// v must be non-negative. One __syncthreads per call; callers alternate `buf`.
__device__ __forceinline__ unsigned block_argmax(float v, unsigned i, int buf,
                                                 unsigned* pv, unsigned* pi,
                                                 int warp, int lane)
{
    unsigned vb = __float_as_uint(v);            // monotone for v >= 0
    unsigned m1 = __reduce_max_sync(0xFFFFFFFFu, vb);
    unsigned c1 = (vb == m1) ? i : 0xFFFFFFFFu;
    unsigned i1 = __reduce_min_sync(0xFFFFFFFFu, c1);
    if (lane == 0) { pv[buf * 32 + warp] = m1; pi[buf * 32 + warp] = i1; }
    __syncthreads();
    unsigned v2 = pv[buf * 32 + lane];
    unsigned i2 = pi[buf * 32 + lane];
    unsigned m2 = __reduce_max_sync(0xFFFFFFFFu, v2);
    unsigned c2 = (v2 == m2) ? i2 : 0xFFFFFFFFu;
    return __reduce_min_sync(0xFFFFFFFFu, c2);
}

extern "C" __global__ void __launch_bounds__(TT, 1)
fps_kernel(const float* __restrict__ pts,   // [B, 3, N]
           float* __restrict__ out_pts)     // [B, M, 3]
{
    extern __shared__ unsigned char smraw[];
    float*    sx   = (float*)smraw;
    float*    sy   = sx + NN;
    float*    sz   = sy + NN;
    unsigned* pv   = (unsigned*)(sz + NN);
    unsigned* pi   = pv + 64;
    float*    cent = (float*)(pi + 64);

    const int b    = blockIdx.x;
    const int tid  = threadIdx.x;
    const int lane = tid & 31;
    const int warp = tid >> 5;

    const float* px = pts + (size_t)b * 3 * NN;
    const float* py = px + NN;
    const float* pz = px + 2 * NN;

    // Packed coords: pair j holds points (tid + 2j*TT, tid + (2j+1)*TT).
    unsigned long long X2[NPAIR], Y2[NPAIR], Z2[NPAIR];
    float dr[PPT];
    float s1 = 0.f, s2 = 0.f, s3 = 0.f;
    float xs[PPT], ys[PPT], zs[PPT];
    #pragma unroll
    for (int k = 0; k < PPT; k++) {
        int n = tid + k * TT;               // coalesced
        float x = px[n], y = py[n], z = pz[n];
        xs[k] = x; ys[k] = y; zs[k] = z;
        sx[n] = x; sy[n] = y; sz[n] = z;
        s1 += x; s2 += y; s3 += z;
        dr[k] = 1e10f;
    }
    #pragma unroll
    for (int j = 0; j < NPAIR; j++) {
        X2[j] = pack2(xs[2 * j], xs[2 * j + 1]);
        Y2[j] = pack2(ys[2 * j], ys[2 * j + 1]);
        Z2[j] = pack2(zs[2 * j], zs[2 * j + 1]);
    }

    // Deterministic centroid (identical to round-1 numerics).
    s1 = warp_sum(s1); s2 = warp_sum(s2); s3 = warp_sum(s3);
    if (lane == 0) { cent[warp] = s1; cent[32 + warp] = s2; cent[64 + warp] = s3; }
    __syncthreads();
    float cx = warp_sum(cent[lane])      * (1.0f / NN);
    float cy = warp_sum(cent[32 + lane]) * (1.0f / NN);
    float cz = warp_sum(cent[64 + lane]) * (1.0f / NN);

    // d0 = ||p - centroid||^2 (scalar, exactly as round 1).
    float best = -1.0f; unsigned bi = 0;
    #pragma unroll
    for (int k = 0; k < PPT; k++) {
        float dx = xs[k] - cx, dy = ys[k] - cy, dz = zs[k] - cz;
        float d = __fadd_rn(__fadd_rn(__fmul_rn(dx, dx), __fmul_rn(dy, dy)),
                            __fmul_rn(dz, dz));
        if (d > best) { best = d; bi = (unsigned)(tid + k * TT); }
    }
    unsigned far = block_argmax(best, bi, 0, pv, pi, warp, lane);

    float* outp = out_pts + (size_t)b * MM * 3;
    int*   idxp = g_idx + b * MM;

    for (int m = 0; m < MM; m++) {
        float qx = sx[far], qy = sy[far], qz = sz[far];
        if (tid == 0) {
            idxp[m] = (int)far;
            outp[m * 3 + 0] = qx;
            outp[m * 3 + 1] = qy;
            outp[m * 3 + 2] = qz;
        }
        // Packed negated query (x - q == x + (-q), exact).
        unsigned long long nqx2 = pack2(-qx, -qx);
        unsigned long long nqy2 = pack2(-qy, -qy);
        unsigned long long nqz2 = pack2(-qz, -qz);

        float mx = -1.0f;
        #pragma unroll
        for (int j = 0; j < NPAIR; j++) {
            unsigned long long dx2 = add2(X2[j], nqx2);
            unsigned long long dy2 = add2(Y2[j], nqy2);
            unsigned long long dz2 = add2(Z2[j], nqz2);
            // d = (dx*dx + dy*dy) + dz*dz, RN per lane, no contraction:
            unsigned long long d2 = add2(add2(mul2(dx2, dx2), mul2(dy2, dy2)),
                                         mul2(dz2, dz2));
            float dlo, dhi;
            unpack2(d2, dlo, dhi);
            float nd0 = fminf(dr[2 * j],     dlo);
            float nd1 = fminf(dr[2 * j + 1], dhi);
            dr[2 * j] = nd0; dr[2 * j + 1] = nd1;
            mx = fmaxf(mx, nd0);
            mx = fmaxf(mx, nd1);
        }
        // Recover smallest global index attaining mx (exact bit equality;
        // descending k so the lowest k wins).
        unsigned bix = 0;
        #pragma unroll
        for (int k = PPT - 1; k >= 0; k--)
            if (dr[k] == mx) bix = (unsigned)(tid + k * TT);

        far = block_argmax(mx, bix, (m + 1) & 1, pv, pi, warp, lane);
    }
}

extern "C" __global__ void gather_kernel(const float* __restrict__ feats,  // [B, C, N]
                                         float* __restrict__ out_feats)   // [B, M, C]
{
    int bm = blockIdx.x;                 // b * MM + m
    int b  = bm >> 11;                   // MM = 2048
    int n  = g_idx[bm];
    int c  = threadIdx.x;                // 0..CC-1
    out_feats[(size_t)bm * CC + c] = feats[((size_t)b * CC + c) * NN + n];
}

extern "C" void kernel_launch(void* const* d_in, const int* in_sizes, int n_in,
                              void* d_out, int out_size)
{
    const float* pts   = (const float*)d_in[0];  // [B, 3, N]
    const float* feats = (const float*)d_in[1];  // [B, C, N]
    float* out = (float*)d_out;

    cudaFuncSetAttribute(fps_kernel,
                         cudaFuncAttributeMaxDynamicSharedMemorySize, SMEM_BYTES);

    fps_kernel<<<BB, TT, SMEM_BYTES>>>(pts, out);
    gather_kernel<<<BB * MM, CC>>>(feats, out + (size_t)BB * MM * 3);
}

// round 3
// speedup vs baseline: 1.5255x; 1.1804x over previous
#include <cuda_runtime.h>

// Problem constants (fixed: B=16, N=8192, C=256, num_points=2048)
#define BB   16
#define NN   8192
#define CC   256
#define MM   2048
#define TT   1024          // threads per FPS block
#define PPT  (NN / TT)     // points per thread = 8
#define NPAIR (PPT / 2)    // f32x2 pairs per thread = 4

// Scratch: selected indices, written by FPS kernel, read by gather kernel.
__device__ int g_idx[BB * MM];

// Dynamic smem: sx[NN], sy[NN], sz[NN], pv[64], pi[64], cent[96]
#define SMEM_BYTES (3 * NN * 4 + 64 * 4 + 64 * 4 + 96 * 4)

// ---- packed f32x2 helpers (sm_103a) ---------------------------------------
__device__ __forceinline__ unsigned long long pack2(float lo, float hi) {
    unsigned long long r;
    asm("mov.b64 %0, {%1, %2};" : "=l"(r) : "f"(lo), "f"(hi));
    return r;
}
__device__ __forceinline__ void unpack2(unsigned long long v, float& lo, float& hi) {
    asm("mov.b64 {%0, %1}, %2;" : "=f"(lo), "=f"(hi) : "l"(v));
}
__device__ __forceinline__ unsigned long long add2(unsigned long long a, unsigned long long b) {
    unsigned long long r;
    asm("add.rn.f32x2 %0, %1, %2;" : "=l"(r) : "l"(a), "l"(b));
    return r;
}
__device__ __forceinline__ unsigned long long mul2(unsigned long long a, unsigned long long b) {
    unsigned long long r;
    asm("mul.rn.f32x2 %0, %1, %2;" : "=l"(r) : "l"(a), "l"(b));
    return r;
}
// ---------------------------------------------------------------------------

__device__ __forceinline__ float warp_sum(float x) {
    #pragma unroll
    for (int o = 16; o > 0; o >>= 1)
        x += __shfl_xor_sync(0xFFFFFFFFu, x, o);
    return x;
}

extern "C" __global__ void __launch_bounds__(TT, 1)
fps_kernel(const float* __restrict__ pts,   // [B, 3, N]
           float* __restrict__ out_pts)     // [B, M, 3]
{
    extern __shared__ unsigned char smraw[];
    float*    sx   = (float*)smraw;
    float*    sy   = sx + NN;
    float*    sz   = sy + NN;
    unsigned* pv   = (unsigned*)(sz + NN);   // [64]: [0..32) main loop, [32..64) init
    unsigned* pi   = pv + 64;                // [64]: [0..32) main loop, [32..64) init
    float*    cent = (float*)(pi + 64);

    const int b    = blockIdx.x;
    const int tid  = threadIdx.x;
    const int lane = tid & 31;
    const int warp = tid >> 5;

    const float* px = pts + (size_t)b * 3 * NN;
    const float* py = px + NN;
    const float* pz = px + 2 * NN;

    // Packed coords: pair j holds points (tid + 2j*TT, tid + (2j+1)*TT).
    unsigned long long X2[NPAIR], Y2[NPAIR], Z2[NPAIR];
    float dr[PPT];
    float s1 = 0.f, s2 = 0.f, s3 = 0.f;
    float xs[PPT], ys[PPT], zs[PPT];
    #pragma unroll
    for (int k = 0; k < PPT; k++) {
        int n = tid + k * TT;               // coalesced
        float x = px[n], y = py[n], z = pz[n];
        xs[k] = x; ys[k] = y; zs[k] = z;
        sx[n] = x; sy[n] = y; sz[n] = z;
        s1 += x; s2 += y; s3 += z;
        dr[k] = 1e10f;
    }
    #pragma unroll
    for (int j = 0; j < NPAIR; j++) {
        X2[j] = pack2(xs[2 * j], xs[2 * j + 1]);
        Y2[j] = pack2(ys[2 * j], ys[2 * j + 1]);
        Z2[j] = pack2(zs[2 * j], zs[2 * j + 1]);
    }

    // Deterministic centroid (identical numerics to previous rounds).
    s1 = warp_sum(s1); s2 = warp_sum(s2); s3 = warp_sum(s3);
    if (lane == 0) { cent[warp] = s1; cent[32 + warp] = s2; cent[64 + warp] = s3; }
    __syncthreads();
    float cx = warp_sum(cent[lane])      * (1.0f / NN);
    float cy = warp_sum(cent[32 + lane]) * (1.0f / NN);
    float cz = warp_sum(cent[64 + lane]) * (1.0f / NN);

    // d0 = ||p - centroid||^2, initial farthest (one-shot; uses slots [32..64)).
    float best = -1.0f; unsigned bi = 0;
    #pragma unroll
    for (int k = 0; k < PPT; k++) {
        float dx = xs[k] - cx, dy = ys[k] - cy, dz = zs[k] - cz;
        float d = __fadd_rn(__fadd_rn(__fmul_rn(dx, dx), __fmul_rn(dy, dy)),
                            __fmul_rn(dz, dz));
        if (d > best) { best = d; bi = (unsigned)(tid + k * TT); }
    }
    {
        unsigned vb = __float_as_uint(best);
        unsigned m1 = __reduce_max_sync(0xFFFFFFFFu, vb);
        unsigned c1 = (vb == m1) ? bi : 0xFFFFFFFFu;
        unsigned i1 = __reduce_min_sync(0xFFFFFFFFu, c1);
        if (lane == 0) { pv[32 + warp] = m1; pi[32 + warp] = i1; }
    }
    __syncthreads();
    unsigned far;
    {
        unsigned v2 = pv[32 + lane];
        unsigned i2 = pi[32 + lane];
        unsigned m2 = __reduce_max_sync(0xFFFFFFFFu, v2);
        unsigned c2 = (v2 == m2) ? i2 : 0xFFFFFFFFu;
        far = __reduce_min_sync(0xFFFFFFFFu, c2);
    }

    float* outp = out_pts + (size_t)b * MM * 3;
    int*   idxp = g_idx + b * MM;

    for (int m = 0; m < MM; m++) {
        // Broadcast the selected point's coords (conflict-free broadcast LDS).
        float qx = sx[far], qy = sy[far], qz = sz[far];
        if (tid == 0) {
            idxp[m] = (int)far;
            outp[m * 3 + 0] = qx;
            outp[m * 3 + 1] = qy;
            outp[m * 3 + 2] = qz;
        }
        // Packed negated query (x - q == x + (-q), exact).
        unsigned long long nqx2 = pack2(-qx, -qx);
        unsigned long long nqy2 = pack2(-qy, -qy);
        unsigned long long nqz2 = pack2(-qz, -qz);

        float mx = -1.0f;
        #pragma unroll
        for (int j = 0; j < NPAIR; j++) {
            unsigned long long dx2 = add2(X2[j], nqx2);
            unsigned long long dy2 = add2(Y2[j], nqy2);
            unsigned long long dz2 = add2(Z2[j], nqz2);
            // d = (dx*dx + dy*dy) + dz*dz, RN per lane, no contraction:
            unsigned long long d2 = add2(add2(mul2(dx2, dx2), mul2(dy2, dy2)),
                                         mul2(dz2, dz2));
            float dlo, dhi;
            unpack2(d2, dlo, dhi);
            float nd0 = fminf(dr[2 * j],     dlo);
            float nd1 = fminf(dr[2 * j + 1], dhi);
            dr[2 * j] = nd0; dr[2 * j + 1] = nd1;
            mx = fmaxf(mx, fmaxf(nd0, nd1));
        }

        // Phase 1: value-only block max.
        unsigned vb = __float_as_uint(mx);           // monotone for mx >= 0
        unsigned m1 = __reduce_max_sync(0xFFFFFFFFu, vb);
        if (lane == 0) pv[warp] = m1;
        __syncthreads();                              // bar1
        unsigned m2 = __reduce_max_sync(0xFFFFFFFFu, pv[lane]);

        // Phase 2: only winning warp(s) recover the index (warp-uniform branch).
        unsigned cand = 0xFFFFFFFFu;
        if (m1 == m2) {
            #pragma unroll
            for (int k = PPT - 1; k >= 0; k--)        // descending k -> lowest idx
                if (__float_as_uint(dr[k]) == m2) cand = (unsigned)(tid + k * TT);
            cand = __reduce_min_sync(0xFFFFFFFFu, cand);
        }
        if (lane == 0) pi[warp] = cand;
        __syncthreads();                              // bar2
        far = __reduce_min_sync(0xFFFFFFFFu, pi[lane]);
    }
}

extern "C" __global__ void gather_kernel(const float* __restrict__ feats,  // [B, C, N]
                                         float* __restrict__ out_feats)   // [B, M, C]
{
    int bm = blockIdx.x;                 // b * MM + m
    int b  = bm >> 11;                   // MM = 2048
    int n  = g_idx[bm];
    int c  = threadIdx.x;                // 0..CC-1
    out_feats[(size_t)bm * CC + c] = feats[((size_t)b * CC + c) * NN + n];
}

extern "C" void kernel_launch(void* const* d_in, const int* in_sizes, int n_in,
                              void* d_out, int out_size)
{
    const float* pts   = (const float*)d_in[0];  // [B, 3, N]
    const float* feats = (const float*)d_in[1];  // [B, C, N]
    float* out = (float*)d_out;

    cudaFuncSetAttribute(fps_kernel,
                         cudaFuncAttributeMaxDynamicSharedMemorySize, SMEM_BYTES);

    fps_kernel<<<BB, TT, SMEM_BYTES>>>(pts, out);
    gather_kernel<<<BB * MM, CC>>>(feats, out + (size_t)BB * MM * 3);
}